// round 7
// baseline (speedup 1.0000x reference)
#include <cuda_runtime.h>
#include <math.h>

#define TPB 128
#define WSTRIDE 36              // window floats/token (144B, vec4-aligned, LDS.128 conflict-free)
#define SSTRIDE 17              // stat row stride (odd -> conflict-free scalar LDS/STS)
#define NEG_INF (-3.402823466e+38f)

__device__ __forceinline__ void cp_async16(void* smem_dst, const void* gmem_src) {
    unsigned saddr = (unsigned)__cvta_generic_to_shared(smem_dst);
    asm volatile("cp.async.ca.shared.global [%0], [%1], 16;\n"
                 :: "r"(saddr), "l"(gmem_src));
}
__device__ __forceinline__ void cp_async_commit_wait() {
    asm volatile("cp.async.commit_group;\n");
    asm volatile("cp.async.wait_group 0;\n" ::: "memory");
}

__global__ __launch_bounds__(TPB, 8) void dfine_lqe_kernel(
    const float* __restrict__ scores,   // (tokens, 80)
    const float* __restrict__ pc,       // (tokens, 132)
    const float* __restrict__ W1,       // (20, 64)
    const float* __restrict__ b1,       // (64,)
    const float* __restrict__ W2,       // (64, 1)
    const float* __restrict__ b2,       // (1,)
    float* __restrict__ out,            // (tokens, 80)
    int tokens)
{
    __shared__ float sW1e[1024];            // effective W1, [j][16] (mean folded in)
    __shared__ float sB1[64];
    __shared__ float sW2[64];
    __shared__ float sQ[TPB];
    __shared__ float sStat[TPB * SSTRIDE];  // 16 probs per token
    __shared__ float sPC[TPB * WSTRIDE];    // staged 36-float windows

    const int tid = threadIdx.x;
    const int t0  = blockIdx.x * TPB;
    const int ntb = min(TPB, tokens - t0);

    // ---- stage effective weights: W1e[j][g*4+k] = W1[g*5+k][j] + 0.25*W1[g*5+4][j] ----
    #pragma unroll 2
    for (int i = tid; i < 1024; i += TPB) {
        int j = i >> 4;
        int d = i & 15;
        int g = d >> 2, k = d & 3;
        sW1e[i] = W1[(g * 5 + k) * 64 + j] + 0.25f * W1[(g * 5 + 4) * 64 + j];
    }
    if (tid < 64) {
        sB1[tid] = b1[tid];
        sW2[tid] = W2[tid];
    }
    __syncthreads();

    const float4* pc4    = reinterpret_cast<const float4*>(pc);
    float*        srow   = &sPC[tid * WSTRIDE];
    float*        statrw = &sStat[tid * SSTRIDE];
    const float4* w4row  = reinterpret_cast<const float4*>(srow);

    #pragma unroll 1
    for (int g = 0; g < 4; g++) {
        if (g) __syncthreads();                  // readers done with prev stage

        // ---- coalesced async stage: window vec4 base (g*33)>>2, 9 vec4/token ----
        const size_t gbase = (size_t)t0 * 33 + ((g * 33) >> 2);
        #pragma unroll
        for (int s = 0; s < 9; s++) {
            int i   = tid + s * TPB;             // 0..1151
            int row = i / 9;
            int v   = i - row * 9;
            if (row < ntb)
                cp_async16(&sPC[row * WSTRIDE + v * 4], &pc4[gbase + (size_t)row * 33 + v]);
        }
        cp_async_commit_wait();
        __syncthreads();

        if (tid < ntb) {
            // poison the 3 invalid window slots: {0..g-1} and {g+33..35}
            #pragma unroll
            for (int i = 0; i < 3; i++) {
                int pos = (i < g) ? i : (33 + i);
                srow[pos] = NEG_INF;
            }
            // PASS 1: branchless top-4 over all 36 (poisons never win)
            float m0 = NEG_INF, m1 = NEG_INF, m2 = NEG_INF, m3 = NEG_INF;
            #pragma unroll
            for (int v = 0; v < 9; v++) {
                float4 t = w4row[v];
                float e0 = t.x, e1 = t.y, e2 = t.z, e3 = t.w;
                #pragma unroll
                for (int e = 0; e < 4; e++) {
                    float val = (e == 0) ? e0 : (e == 1) ? e1 : (e == 2) ? e2 : e3;
                    float a1 = fminf(m0, val); m0 = fmaxf(m0, val);
                    float a2 = fminf(m1, a1);  m1 = fmaxf(m1, a1);
                    float a3 = fminf(m2, a2);  m2 = fmaxf(m2, a2);
                    m3 = fmaxf(m3, a3);
                }
            }
            // PASS 2: sum of exp (poisoned slots underflow to 0 exactly)
            float ssum = 0.0f;
            #pragma unroll
            for (int v = 0; v < 9; v++) {
                float4 t = w4row[v];
                ssum += __expf(t.x - m0);
                ssum += __expf(t.y - m0);
                ssum += __expf(t.z - m0);
                ssum += __expf(t.w - m0);
            }
            float inv = 1.0f / ssum;
            statrw[g * 4 + 0] = inv;                     // exp(m0-m0)/S
            statrw[g * 4 + 1] = __expf(m1 - m0) * inv;
            statrw[g * 4 + 2] = __expf(m2 - m0) * inv;
            statrw[g * 4 + 3] = __expf(m3 - m0) * inv;
        }
    }

    // ---- tiny MLP with mean-folded weights: q = W2 . relu(W1e^T p + b1) + b2 ----
    if (tid < ntb) {
        float stat[16];
        #pragma unroll
        for (int d = 0; d < 16; d++) stat[d] = statrw[d];

        float q = b2[0];
        #pragma unroll 4
        for (int j = 0; j < 64; j++) {
            const float4* w4 = reinterpret_cast<const float4*>(&sW1e[j * 16]);
            float acc = sB1[j];
            float4 wa = w4[0], wb = w4[1], wc = w4[2], wd = w4[3];
            acc = fmaf(stat[0],  wa.x, acc); acc = fmaf(stat[1],  wa.y, acc);
            acc = fmaf(stat[2],  wa.z, acc); acc = fmaf(stat[3],  wa.w, acc);
            acc = fmaf(stat[4],  wb.x, acc); acc = fmaf(stat[5],  wb.y, acc);
            acc = fmaf(stat[6],  wb.z, acc); acc = fmaf(stat[7],  wb.w, acc);
            acc = fmaf(stat[8],  wc.x, acc); acc = fmaf(stat[9],  wc.y, acc);
            acc = fmaf(stat[10], wc.z, acc); acc = fmaf(stat[11], wc.w, acc);
            acc = fmaf(stat[12], wd.x, acc); acc = fmaf(stat[13], wd.y, acc);
            acc = fmaf(stat[14], wd.z, acc); acc = fmaf(stat[15], wd.w, acc);
            q = fmaf(fmaxf(acc, 0.0f), sW2[j], q);
        }
        sQ[tid] = q;
    }
    __syncthreads();

    // ---- coalesced epilogue: out = scores + q[token], float4 ----
    {
        const float4* sc4  = reinterpret_cast<const float4*>(scores) + (size_t)t0 * 20;
        float4*       out4 = reinterpret_cast<float4*>(out) + (size_t)t0 * 20;
        const int nvec = ntb * 20;
        #pragma unroll 4
        for (int i = tid; i < nvec; i += TPB) {
            int row = i / 20;
            float4 s = sc4[i];
            float qq = sQ[row];
            s.x += qq; s.y += qq; s.z += qq; s.w += qq;
            out4[i] = s;
        }
    }
}

extern "C" void kernel_launch(void* const* d_in, const int* in_sizes, int n_in,
                              void* d_out, int out_size)
{
    const float* scores = (const float*)d_in[0];
    const float* pc     = (const float*)d_in[1];
    const float* W1     = (const float*)d_in[2];
    const float* b1     = (const float*)d_in[3];
    const float* W2     = (const float*)d_in[4];
    const float* b2     = (const float*)d_in[5];
    float* out = (float*)d_out;

    const int tokens = in_sizes[1] / 132;
    const int nblocks = (tokens + TPB - 1) / TPB;

    dfine_lqe_kernel<<<nblocks, TPB>>>(scores, pc, W1, b1, W2, b2, out, tokens);
}

// round 8
// speedup vs baseline: 1.0915x; 1.0915x over previous
#include <cuda_runtime.h>
#include <math.h>

#define TPB 128
#define NEG_INF (-3.402823466e+38f)

__global__ __launch_bounds__(TPB, 8) void dfine_lqe_kernel(
    const float* __restrict__ scores,   // (tokens, 80)
    const float* __restrict__ pc,       // (tokens, 132)
    const float* __restrict__ W1,       // (20, 64)
    const float* __restrict__ b1,       // (64,)
    const float* __restrict__ W2,       // (64, 1)
    const float* __restrict__ b2,       // (1,)
    float* __restrict__ out,            // (tokens, 80)
    int tokens)
{
    __shared__ float sW1e[64 * 20];     // effective W1 (mean folded), row-major [j][16], rows padded to 20
    __shared__ float sB1[64];
    __shared__ float sW2[64];
    __shared__ float sQ[TPB];

    const int tid = threadIdx.x;
    const int t0  = blockIdx.x * TPB;
    const int ntb = min(TPB, tokens - t0);

    // ---- stage effective weights: W1e[j][4g+k] = W1[5g+k][j] + 0.25*W1[5g+4][j] ----
    #pragma unroll 2
    for (int i = tid; i < 1280; i += TPB) {
        int j = i / 20;
        int d = i - j * 20;
        float v = 0.0f;
        if (d < 16) {
            int g = d >> 2, k = d & 3;
            v = W1[(g * 5 + k) * 64 + j] + 0.25f * W1[(g * 5 + 4) * 64 + j];
        }
        sW1e[i] = v;
    }
    if (tid < 64) {
        sB1[tid] = b1[tid];
        sW2[tid] = W2[tid];
    }
    __syncthreads();

    const int w    = tid >> 5;          // warp id (0..3)
    const int lane = tid & 31;
    const int sub  = lane >> 3;         // token slot within warp (0..3)
    const int li   = lane & 7;          // lane within 8-lane token group

    const float4* pc4 = reinterpret_cast<const float4*>(pc);
    const float bias2 = b2[0];
    const unsigned FULL = 0xFFFFFFFFu;

    // warp w covers block tokens [32w, 32w+32) in 8 passes of 4 tokens
    #pragma unroll 1
    for (int p = 0; p < 8; p++) {
        const int tib = w * 32 + p * 4 + sub;     // token index within block
        const bool tv = (tib < ntb);
        const int tok = t0 + tib;

        // ---- batched cooperative loads: 4 groups x (1 vec4 + 1 scalar) per lane ----
        float4 vv[4];
        float  sc[4];
        {
            const size_t rv4 = (size_t)tok * 33;
            const size_t rf  = (size_t)tok * 132;
            #pragma unroll
            for (int g = 0; g < 4; g++) {
                const int bg = (33 * g) >> 2;     // {0,8,16,24}
                if (tv) vv[g] = pc4[rv4 + bg + li];
                else    vv[g] = make_float4(NEG_INF, NEG_INF, NEG_INF, NEG_INF);
                sc[g] = (tv && li < 4) ? pc[rf + 4 * bg + 32 + li] : NEG_INF;
            }
        }

        float stat[16];

        #pragma unroll
        for (int g = 0; g < 4; g++) {
            // window positions: vec4 -> 4*li+e, scalar -> 32+li; valid = [g, g+33)
            float4 t = vv[g];
            float x0 = (4 * li + 0 >= g) ? t.x : NEG_INF;
            float x1 = (4 * li + 1 >= g) ? t.y : NEG_INF;
            float x2 = (4 * li + 2 >= g) ? t.z : NEG_INF;
            float x3 = t.w;                               // 4*li+3 >= 3 >= g always
            float x4 = (li <= g) ? sc[g] : NEG_INF;       // 32+li < g+33  <=>  li <= g

            // local branchless top-4 (descending)
            float m0 = NEG_INF, m1 = NEG_INF, m2 = NEG_INF, m3 = NEG_INF;
            #pragma unroll
            for (int e = 0; e < 5; e++) {
                float v  = (e == 0) ? x0 : (e == 1) ? x1 : (e == 2) ? x2 : (e == 3) ? x3 : x4;
                float a1 = fminf(m0, v); m0 = fmaxf(m0, v);
                float a2 = fminf(m1, a1); m1 = fmaxf(m1, a1);
                float a3 = fminf(m2, a2); m2 = fmaxf(m2, a2);
                m3 = fmaxf(m3, a3);
            }
            const float mloc = m0;
            // local sum of exp (invalid slots: exp(huge negative) == 0)
            float s = __expf(x0 - mloc) + __expf(x1 - mloc) + __expf(x2 - mloc)
                    + __expf(x3 - mloc) + __expf(x4 - mloc);

            // merge top-4 lists across the 8 lanes (bitonic top-4 merge, 3 rounds)
            #pragma unroll
            for (int r = 1; r <= 4; r <<= 1) {
                float bb0 = __shfl_xor_sync(FULL, m0, r);
                float bb1 = __shfl_xor_sync(FULL, m1, r);
                float bb2 = __shfl_xor_sync(FULL, m2, r);
                float bb3 = __shfl_xor_sync(FULL, m3, r);
                float c0 = fmaxf(m0, bb3);
                float c1 = fmaxf(m1, bb2);
                float c2 = fmaxf(m2, bb1);
                float c3 = fmaxf(m3, bb0);
                // bitonic sort-4 (descending)
                float lo;
                lo = fminf(c0, c2); c0 = fmaxf(c0, c2); c2 = lo;
                lo = fminf(c1, c3); c1 = fmaxf(c1, c3); c3 = lo;
                lo = fminf(c0, c1); c0 = fmaxf(c0, c1); c1 = lo;
                lo = fminf(c2, c3); c2 = fmaxf(c2, c3); c3 = lo;
                m0 = c0; m1 = c1; m2 = c2; m3 = c3;
            }

            // global sum: rescale local sums to global max, reduce over 8 lanes
            float sg = s * __expf(mloc - m0);
            sg += __shfl_xor_sync(FULL, sg, 1);
            sg += __shfl_xor_sync(FULL, sg, 2);
            sg += __shfl_xor_sync(FULL, sg, 4);

            float inv = 1.0f / sg;
            stat[g * 4 + 0] = inv;                       // exp(m0-m0)/S
            stat[g * 4 + 1] = __expf(m1 - m0) * inv;
            stat[g * 4 + 2] = __expf(m2 - m0) * inv;
            stat[g * 4 + 3] = __expf(m3 - m0) * inv;
        }

        // ---- MLP split 8 ways: lane li handles rows j = li + 8*i ----
        float q = 0.0f;
        #pragma unroll
        for (int i8 = 0; i8 < 8; i8++) {
            int j = li + 8 * i8;
            const float4* w4 = reinterpret_cast<const float4*>(&sW1e[j * 20]);
            float acc = sB1[j];
            float4 wa = w4[0], wb = w4[1], wc = w4[2], wd = w4[3];
            acc = fmaf(stat[0],  wa.x, acc); acc = fmaf(stat[1],  wa.y, acc);
            acc = fmaf(stat[2],  wa.z, acc); acc = fmaf(stat[3],  wa.w, acc);
            acc = fmaf(stat[4],  wb.x, acc); acc = fmaf(stat[5],  wb.y, acc);
            acc = fmaf(stat[6],  wb.z, acc); acc = fmaf(stat[7],  wb.w, acc);
            acc = fmaf(stat[8],  wc.x, acc); acc = fmaf(stat[9],  wc.y, acc);
            acc = fmaf(stat[10], wc.z, acc); acc = fmaf(stat[11], wc.w, acc);
            acc = fmaf(stat[12], wd.x, acc); acc = fmaf(stat[13], wd.y, acc);
            acc = fmaf(stat[14], wd.z, acc); acc = fmaf(stat[15], wd.w, acc);
            q = fmaf(fmaxf(acc, 0.0f), sW2[j], q);
        }
        q += __shfl_xor_sync(FULL, q, 1);
        q += __shfl_xor_sync(FULL, q, 2);
        q += __shfl_xor_sync(FULL, q, 4);
        if (li == 0 && tv) sQ[tib] = q + bias2;
    }
    __syncthreads();

    // ---- coalesced epilogue: out = scores + q[token], float4 ----
    {
        const float4* sc4  = reinterpret_cast<const float4*>(scores) + (size_t)t0 * 20;
        float4*       out4 = reinterpret_cast<float4*>(out) + (size_t)t0 * 20;
        const int nvec = ntb * 20;
        #pragma unroll 4
        for (int i = tid; i < nvec; i += TPB) {
            int row = i / 20;
            float4 s = sc4[i];
            float qq = sQ[row];
            s.x += qq; s.y += qq; s.z += qq; s.w += qq;
            out4[i] = s;
        }
    }
}

extern "C" void kernel_launch(void* const* d_in, const int* in_sizes, int n_in,
                              void* d_out, int out_size)
{
    const float* scores = (const float*)d_in[0];
    const float* pc     = (const float*)d_in[1];
    const float* W1     = (const float*)d_in[2];
    const float* b1     = (const float*)d_in[3];
    const float* W2     = (const float*)d_in[4];
    const float* b2     = (const float*)d_in[5];
    float* out = (float*)d_out;

    const int tokens = in_sizes[1] / 132;
    const int nblocks = (tokens + TPB - 1) / TPB;

    dfine_lqe_kernel<<<nblocks, TPB>>>(scores, pc, W1, b1, W2, b2, out, tokens);
}